// round 2
// baseline (speedup 1.0000x reference)
#include <cuda_runtime.h>
#include <cuda_bf16.h>
#include <cstdint>

typedef unsigned long long u64;

// device scratch (no allocations allowed -> __device__ globals)
__device__ __align__(16) float g_Wct[256 * 128];      // Wc^T : [c][d], c<128 = Wz, c>=128 = Wx
__device__ __align__(16) float g_W2t[2 * 256 * 128];  // W2^T per block: [blk][j][d]
__device__ __align__(16) float g_G[256 * 128];        // codebook + codebook@Wz^T + bc
__device__ __align__(16) float g_V[2048 * 128];       // xhat @ Wx^T

// ---- packed f32x2 helpers ----
__device__ __forceinline__ u64 pack2(float lo, float hi) {
    u64 r; asm("mov.b64 %0, {%1, %2};" : "=l"(r) : "f"(lo), "f"(hi)); return r;
}
__device__ __forceinline__ void unpack2(u64 v, float& lo, float& hi) {
    asm("mov.b64 {%0, %1}, %2;" : "=f"(lo), "=f"(hi) : "l"(v));
}
__device__ __forceinline__ u64 ffma2(u64 a, u64 b, u64 c) {
    u64 d; asm("fma.rn.f32x2 %0, %1, %2, %3;" : "=l"(d) : "l"(a), "l"(b), "l"(c)); return d;
}
__device__ __forceinline__ u64 fadd2(u64 a, u64 b) {
    u64 d; asm("add.rn.f32x2 %0, %1, %2;" : "=l"(d) : "l"(a), "l"(b)); return d;
}
__device__ __forceinline__ u64 u64min(u64 a, u64 b) { return a < b ? a : b; }

// ---- cp.async helpers ----
__device__ __forceinline__ void cp16(void* smem_dst, const void* gsrc) {
    uint32_t s = (uint32_t)__cvta_generic_to_shared(smem_dst);
    asm volatile("cp.async.cg.shared.global [%0], [%1], 16;" :: "r"(s), "l"(gsrc));
}
__device__ __forceinline__ void cp_commit() { asm volatile("cp.async.commit_group;"); }
__device__ __forceinline__ void cp_wait1()  { asm volatile("cp.async.wait_group 1;"); }
__device__ __forceinline__ void cp_wait0()  { asm volatile("cp.async.wait_group 0;"); }

// ---- prep kernels ----
__global__ void k_wct(const float* __restrict__ Wc) {
    int c = blockIdx.x, d = threadIdx.x;
    g_Wct[c * 128 + d] = Wc[d * 256 + c];
}
__global__ void k_w2t(const float* __restrict__ W2_0, const float* __restrict__ W2_1) {
    int blk = blockIdx.x >> 8, j = blockIdx.x & 255, d = threadIdx.x;
    const float* W2 = blk ? W2_1 : W2_0;
    g_W2t[blk * 32768 + j * 128 + d] = W2[d * 256 + j];
}
__global__ void k_G(const float* __restrict__ cb, const float* __restrict__ bc) {
    int k = blockIdx.x, d = threadIdx.x;
    __shared__ float s_cb[128];
    s_cb[d] = cb[k * 128 + d];
    __syncthreads();
    float acc = 0.f;
#pragma unroll 4
    for (int e = 0; e < 128; ++e) acc = fmaf(s_cb[e], g_Wct[e * 128 + d], acc);
    g_G[k * 128 + d] = s_cb[d] + acc + bc[d];
}
__global__ void k_V(const float* __restrict__ xhat) {
    int b = blockIdx.x, d = threadIdx.x;
    __shared__ float s_r[128];
    s_r[d] = xhat[b * 128 + d];
    __syncthreads();
    float acc = 0.f;
#pragma unroll 4
    for (int e = 0; e < 128; ++e) acc = fmaf(s_r[e], g_Wct[(128 + e) * 128 + d], acc);
    g_V[b * 128 + d] = acc;
}

// ---- main fused kernel ----
// smem (bytes): s_z 512*33 u64 =135168 | s_w1 2*544 u64 =8704 | s_w2 8704 |
//               s_xh 512 | s_x 512 | s_red 128
#define OFF_W1  135168
#define OFF_W2  (OFF_W1 + 8704)
#define OFF_XH  (OFF_W2 + 8704)
#define OFF_X   (OFF_XH + 512)
#define OFF_RED (OFF_X + 512)
#define SMEM_TOTAL (OFF_RED + 128)

__device__ __forceinline__ void load_tile(u64* dstW1, u64* dstW2,
                                          const float* __restrict__ W1g,
                                          const float* __restrict__ W2g,
                                          int jt, int t) {
    int jj = t >> 5, c = t & 31;                        // 8 rows x 32 16B chunks
    int f2 = jj * 68 + ((c < 16) ? 2 * c : 2 * c + 2);  // halves at +0 / +34 u64
    cp16(dstW1 + f2, W1g + (jt * 8 + jj) * 128 + c * 4);
    cp16(dstW2 + f2, W2g + (jt * 8 + jj) * 128 + c * 4);
}

__global__ __launch_bounds__(256, 1) void k_main(const float* __restrict__ xhat,
                                                 const float* __restrict__ x,
                                                 const float* __restrict__ W1_0,
                                                 const float* __restrict__ W1_1,
                                                 float* __restrict__ out,
                                                 int bs) {
    extern __shared__ unsigned char sm[];
    u64*   s_z   = (u64*)sm;
    u64*   s_w1  = (u64*)(sm + OFF_W1);
    u64*   s_w2  = (u64*)(sm + OFF_W2);
    float* s_xh  = (float*)(sm + OFF_XH);
    float* s_x   = (float*)(sm + OFF_X);
    u64*   s_red = (u64*)(sm + OFF_RED);

    const int b = blockIdx.x;
    const int t = threadIdx.x;
    const int half = t & 1;          // which 64-d half
    const int p = t >> 1;            // row pair id
    const int r0 = p, r1 = p + 128;
    const int dbase = half * 64;

    if (t < 128) s_xh[t] = xhat[b * 128 + t];
    else         s_x[t - 128] = x[b * 128 + (t - 128)];

    // z0 = G[k] + v[b] (residual lives in registers, snapshot in smem for GEMM1)
    u64 acc0[32], acc1[32];
    {
        const u64* Gp0 = (const u64*)(g_G + r0 * 128 + dbase);
        const u64* Gp1 = (const u64*)(g_G + r1 * 128 + dbase);
        const u64* Vp  = (const u64*)(g_V + b * 128 + dbase);
#pragma unroll
        for (int i = 0; i < 32; ++i) {
            u64 vv = Vp[i];
            acc0[i] = fadd2(Gp0[i], vv);
            acc1[i] = fadd2(Gp1[i], vv);
            s_z[t * 33 + i] = acc0[i];
            s_z[(t + 256) * 33 + i] = acc1[i];
        }
    }

    for (int blk = 0; blk < 2; ++blk) {
        const float* W1g = blk ? W1_1 : W1_0;
        const float* W2g = g_W2t + blk * 32768;

        load_tile(s_w1, s_w2, W1g, W2g, 0, t);
        cp_commit();

        for (int jt = 0; jt < 32; ++jt) {
            const int buf = jt & 1;
            if (jt < 31) {
                load_tile(s_w1 + (buf ^ 1) * 544, s_w2 + (buf ^ 1) * 544, W1g, W2g, jt + 1, t);
                cp_commit();
                cp_wait1();
            } else {
                cp_wait0();
            }
            __syncthreads();   // tile ready (and s_z snapshot visible on first iter)

            const u64* w1 = s_w1 + buf * 544 + half * 34;
            const u64* w2 = s_w2 + buf * 544 + half * 34;

            // GEMM1: partial dots over my 64-d half, 8 hidden units, 2 rows
            u64 ha[8], hb[8];
#pragma unroll
            for (int jj = 0; jj < 8; ++jj) { ha[jj] = 0ull; hb[jj] = 0ull; }
#pragma unroll 4
            for (int i = 0; i < 32; ++i) {
                u64 za = s_z[t * 33 + i];
                u64 zb = s_z[(t + 256) * 33 + i];
#pragma unroll
                for (int jj = 0; jj < 8; ++jj) {
                    u64 w = w1[jj * 68 + i];
                    ha[jj] = ffma2(za, w, ha[jj]);
                    hb[jj] = ffma2(zb, w, hb[jj]);
                }
            }
            // pair-reduce (lanes t, t^1 share a row), relu, GEMM2 accumulate
#pragma unroll
            for (int jj = 0; jj < 8; ++jj) {
                float lo, hi, h0, h1;
                unpack2(ha[jj], lo, hi); h0 = lo + hi;
                unpack2(hb[jj], lo, hi); h1 = lo + hi;
                h0 += __shfl_xor_sync(0xffffffffu, h0, 1);
                h1 += __shfl_xor_sync(0xffffffffu, h1, 1);
                h0 = fmaxf(h0, 0.f);
                h1 = fmaxf(h1, 0.f);
                u64 hh0 = pack2(h0, h0), hh1 = pack2(h1, h1);
#pragma unroll
                for (int i = 0; i < 32; ++i) {
                    u64 w = w2[jj * 68 + i];
                    acc0[i] = ffma2(hh0, w, acc0[i]);
                    acc1[i] = ffma2(hh1, w, acc1[i]);
                }
            }
            __syncthreads();   // reads of this buf done before next overwrite
        }

        if (blk == 0) {        // refresh z snapshot for second MLP block
#pragma unroll
            for (int i = 0; i < 32; ++i) {
                s_z[t * 33 + i] = acc0[i];
                s_z[(t + 256) * 33 + i] = acc1[i];
            }
            __syncthreads();
        }
    }

    // epilogue: dist = ||z + xhat - x||^2 ; argmin with first-index tie-break
    float ds0 = 0.f, ds1 = 0.f;
#pragma unroll
    for (int i = 0; i < 32; ++i) {
        int d = dbase + 2 * i;
        float u0 = s_xh[d] - s_x[d];
        float u1 = s_xh[d + 1] - s_x[d + 1];
        float lo, hi;
        unpack2(acc0[i], lo, hi);
        float e0 = lo + u0, e1 = hi + u1;
        ds0 = fmaf(e0, e0, fmaf(e1, e1, ds0));
        unpack2(acc1[i], lo, hi);
        e0 = lo + u0; e1 = hi + u1;
        ds1 = fmaf(e0, e0, fmaf(e1, e1, ds1));
    }
    ds0 += __shfl_xor_sync(0xffffffffu, ds0, 1);
    ds1 += __shfl_xor_sync(0xffffffffu, ds1, 1);

    u64 k0 = ((u64)__float_as_uint(ds0) << 32) | (unsigned)r0;
    u64 k1 = ((u64)__float_as_uint(ds1) << 32) | (unsigned)r1;
    u64 km = u64min(k0, k1);
#pragma unroll
    for (int off = 16; off; off >>= 1)
        km = u64min(km, __shfl_xor_sync(0xffffffffu, km, off));
    if ((t & 31) == 0) s_red[t >> 5] = km;
    __syncthreads();
    if (t == 0) {
        u64 m = s_red[0];
#pragma unroll
        for (int w = 1; w < 8; ++w) m = u64min(m, s_red[w]);
        s_red[0] = m;
        out[b] = (float)(unsigned)(m & 0xffffffffu);
    }
    __syncthreads();

    int code = (int)(unsigned)(s_red[0] & 0xffffffffu);
    u64* od = (u64*)(out + bs + b * 128 + dbase);
    if (r0 == code) {
#pragma unroll
        for (int i = 0; i < 32; ++i) od[i] = acc0[i];   // delta = cand - xhat = z
    } else if (r1 == code) {
#pragma unroll
        for (int i = 0; i < 32; ++i) od[i] = acc1[i];
    }
}

extern "C" void kernel_launch(void* const* d_in, const int* in_sizes, int n_in,
                              void* d_out, int out_size) {
    const float* xhat = (const float*)d_in[0];
    const float* x    = (const float*)d_in[1];
    const float* cb   = (const float*)d_in[2];
    const float* Wc   = (const float*)d_in[3];
    const float* bc   = (const float*)d_in[4];
    const float* W1_0 = (const float*)d_in[5];
    const float* W2_0 = (const float*)d_in[6];
    const float* W1_1 = (const float*)d_in[7];
    const float* W2_1 = (const float*)d_in[8];
    float* out = (float*)d_out;
    const int bs = in_sizes[0] / 128;   // 2048

    static bool attr_set = false;
    if (!attr_set) {
        cudaFuncSetAttribute(k_main, cudaFuncAttributeMaxDynamicSharedMemorySize, SMEM_TOTAL);
        attr_set = true;
    }

    k_wct<<<256, 128>>>(Wc);
    k_w2t<<<512, 128>>>(W2_0, W2_1);
    k_G<<<256, 128>>>(cb, bc);
    k_V<<<bs, 128>>>(xhat);
    k_main<<<bs, 256, SMEM_TOTAL>>>(xhat, x, W1_0, W1_1, out, bs);
}

// round 4
// speedup vs baseline: 1.7687x; 1.7687x over previous
#include <cuda_runtime.h>
#include <cuda_bf16.h>
#include <cstdint>

typedef unsigned long long u64;
typedef unsigned int u32;

#define MARGIN 6.0f

// ---------------- device scratch (allocation-free rule) ----------------
__device__ __align__(16) float g_Wct[256 * 128];        // Wc^T [c][d]
__device__ __align__(16) float g_W2t[2 * 256 * 128];    // W2^T per layer [j][d] (rescue)
__device__ __align__(16) float g_G[256 * 128];          // cb + cb@Wz^T + bc
__device__ __align__(16) float g_V[2048 * 128];         // xhat @ Wx^T
__device__ __align__(16) __nv_bfloat16 g_W1b[2][32768]; // W1 bf16 [j][d] row-major
__device__ __align__(16) __nv_bfloat16 g_W2b[2][32768]; // W2 bf16 [d][h] row-major

// ---------------- PTX helpers ----------------
__device__ __forceinline__ u32 smem_u32(const void* p) {
    u32 a; asm("{ .reg .u64 t; cvta.to.shared.u64 t, %1; cvt.u32.u64 %0, t; }" : "=r"(a) : "l"(p));
    return a;
}
__device__ __forceinline__ void cp16(void* sd, const void* g) {
    u32 s = smem_u32(sd);
    asm volatile("cp.async.cg.shared.global [%0], [%1], 16;" :: "r"(s), "l"(g));
}
#define CP_COMMIT() asm volatile("cp.async.commit_group;")
#define CP_WAIT0()  asm volatile("cp.async.wait_group 0;")

__device__ __forceinline__ void ldsm2(u32& r0, u32& r1, u32 addr) {
    asm volatile("ldmatrix.sync.aligned.m8n8.x2.shared.b16 {%0,%1}, [%2];"
                 : "=r"(r0), "=r"(r1) : "r"(addr));
}
__device__ __forceinline__ void mma16816(float* c, u32 a0, u32 a1, u32 a2, u32 a3,
                                         u32 b0, u32 b1) {
    asm volatile("mma.sync.aligned.m16n8k16.row.col.f32.bf16.bf16.f32 "
                 "{%0,%1,%2,%3},{%4,%5,%6,%7},{%8,%9},{%0,%1,%2,%3};"
                 : "+f"(c[0]), "+f"(c[1]), "+f"(c[2]), "+f"(c[3])
                 : "r"(a0), "r"(a1), "r"(a2), "r"(a3), "r"(b0), "r"(b1));
}
// pack (lo,hi) floats into bf16x2 register
__device__ __forceinline__ u32 pkbf2(float lo, float hi) {
    u32 r; asm("cvt.rn.bf16x2.f32 %0, %1, %2;" : "=r"(r) : "f"(hi), "f"(lo)); return r;
}

// ---------------- prep kernels ----------------
__global__ void k_wct(const float* __restrict__ Wc) {
    int c = blockIdx.x, d = threadIdx.x;
    g_Wct[c * 128 + d] = Wc[d * 256 + c];
}
__global__ void k_w2t(const float* __restrict__ W2_0, const float* __restrict__ W2_1) {
    int blk = blockIdx.x >> 8, j = blockIdx.x & 255, d = threadIdx.x;
    const float* W2 = blk ? W2_1 : W2_0;
    g_W2t[blk * 32768 + j * 128 + d] = W2[d * 256 + j];
}
__global__ void k_G(const float* __restrict__ cb, const float* __restrict__ bc) {
    int k = blockIdx.x, d = threadIdx.x;
    __shared__ float s[128];
    s[d] = cb[k * 128 + d];
    __syncthreads();
    float a = 0.f;
#pragma unroll 4
    for (int e = 0; e < 128; ++e) a = fmaf(s[e], g_Wct[e * 128 + d], a);
    g_G[k * 128 + d] = s[d] + a + bc[d];
}
__global__ void k_V(const float* __restrict__ xhat) {
    int b = blockIdx.x, d = threadIdx.x;
    __shared__ float s[128];
    s[d] = xhat[b * 128 + d];
    __syncthreads();
    float a = 0.f;
#pragma unroll 4
    for (int e = 0; e < 128; ++e) a = fmaf(s[e], g_Wct[(128 + e) * 128 + d], a);
    g_V[b * 128 + d] = a;
}
__global__ void k_wb(const float* __restrict__ W1_0, const float* __restrict__ W1_1,
                     const float* __restrict__ W2_0, const float* __restrict__ W2_1) {
    int idx = blockIdx.x * 256 + threadIdx.x;    // 131072
    int which = idx >> 16, lay = (idx >> 15) & 1, e = idx & 32767;
    if (which == 0) g_W1b[lay][e] = __float2bfloat16((lay ? W1_1 : W1_0)[e]);
    else            g_W2b[lay][e] = __float2bfloat16((lay ? W2_1 : W2_0)[e]);
}

// ---------------- smem map ----------------
#define SM_SU   0
#define SM_DIST 512
#define SM_RED  1536
#define SM_BC   1600
#define SM_CCNT 1604
#define SM_CAND 1608
#define SM_ZC   1664
#define SM_ZB   2176
#define SM_SH   2688
#define SM_W1   4096                 // 2 layers x 64KB (swizzled rows of 256B)
#define SM_W2   (SM_W1 + 131072)     // 64KB (swizzled rows of 512B)
#define SMEMSZ  (SM_W2 + 65536)      // 200704

// ---------------- main kernel ----------------
__global__ __launch_bounds__(512, 1) void k_main(const float* __restrict__ xhat,
                                                 const float* __restrict__ x,
                                                 const float* __restrict__ W1_0,
                                                 const float* __restrict__ W1_1,
                                                 float* __restrict__ out, int bs) {
    extern __shared__ __align__(1024) unsigned char sm[];
    const u32 smb = smem_u32(sm);
    const int t = threadIdx.x, wid = t >> 5, lane = t & 31, b = blockIdx.x;
    float* su = (float*)(sm + SM_SU);
    float* s_dist = (float*)(sm + SM_DIST);
    float* s_red = (float*)(sm + SM_RED);

    // issue weight loads: W1 both layers + W2 layer 0 (XOR-swizzled 16B chunks)
    for (int c = t; c < 8192; c += 512) {
        int lay = c >> 12, e = c & 4095, j = e >> 4, cc = e & 15;
        cp16(sm + SM_W1 + lay * 65536 + j * 256 + ((cc ^ (j & 7)) << 4),
             (const char*)g_W1b[lay] + e * 16);
    }
    for (int c = t; c < 4096; c += 512) {
        int j = c >> 5, cc = c & 31;
        cp16(sm + SM_W2 + j * 512 + ((cc ^ (j & 7)) << 4),
             (const char*)g_W2b[0] + c * 16);
    }
    CP_COMMIT();
    if (t < 128) su[t] = xhat[b * 128 + t] - x[b * 128 + t];
    if (t == 0) *(int*)(sm + SM_CCNT) = 0;

    // Zacc init (fp32 C-fragment layout): rows m0+gr, m0+gr+8; cols nt*8+gc2(+1)
    const int m0 = wid * 16, gr = lane >> 2, gc2 = (lane & 3) * 2;
    float Zacc[16][4];
    {
        const float* Gr0 = g_G + (m0 + gr) * 128;
        const float* Gr1 = Gr0 + 8 * 128;
        const float* Vb = g_V + b * 128;
#pragma unroll
        for (int nt = 0; nt < 16; ++nt) {
            int col = nt * 8 + gc2;
            float2 g0 = *(const float2*)(Gr0 + col);
            float2 g1 = *(const float2*)(Gr1 + col);
            float2 vv = *(const float2*)(Vb + col);
            Zacc[nt][0] = g0.x + vv.x; Zacc[nt][1] = g0.y + vv.y;
            Zacc[nt][2] = g1.x + vv.x; Zacc[nt][3] = g1.y + vv.y;
        }
    }
    CP_WAIT0();
    __syncthreads();

    const int l7 = lane & 7, lh = (lane >> 3) & 1;
    for (int layer = 0; layer < 2; ++layer) {
        if (layer == 1) {   // reload W2 buffer for layer 1
            __syncthreads();
            for (int c = t; c < 4096; c += 512) {
                int j = c >> 5, cc = c & 31;
                cp16(sm + SM_W2 + j * 512 + ((cc ^ (j & 7)) << 4),
                     (const char*)g_W2b[1] + c * 16);
            }
            CP_COMMIT(); CP_WAIT0();
            __syncthreads();
        }
        const u32 w1base = smb + SM_W1 + layer * 65536;
        const u32 w2base = smb + SM_W2;
#pragma unroll 1
        for (int jc = 0; jc < 4; ++jc) {          // 64 hidden units per chunk
            float Hacc[8][4];
#pragma unroll
            for (int nt = 0; nt < 8; ++nt)
#pragma unroll
                for (int e = 0; e < 4; ++e) Hacc[nt][e] = 0.f;
            // GEMM1: H_chunk += Z @ W1_chunk^T
#pragma unroll
            for (int kt = 0; kt < 8; ++kt) {
                u32 a0 = pkbf2(Zacc[2 * kt][0], Zacc[2 * kt][1]);
                u32 a1 = pkbf2(Zacc[2 * kt][2], Zacc[2 * kt][3]);
                u32 a2 = pkbf2(Zacc[2 * kt + 1][0], Zacc[2 * kt + 1][1]);
                u32 a3 = pkbf2(Zacc[2 * kt + 1][2], Zacc[2 * kt + 1][3]);
#pragma unroll
                for (int nt = 0; nt < 8; ++nt) {
                    int row = jc * 64 + nt * 8 + l7;
                    int ch = 2 * kt + lh;
                    u32 addr = w1base + row * 256 + ((ch ^ l7) << 4);
                    u32 b0, b1; ldsm2(b0, b1, addr);
                    mma16816(Hacc[nt], a0, a1, a2, a3, b0, b1);
                }
            }
            // relu + GEMM2: Zacc += relu(H_chunk) @ W2_chunk^T
#pragma unroll
            for (int at = 0; at < 4; ++at) {
#pragma unroll
                for (int e = 0; e < 4; ++e) {
                    Hacc[2 * at][e] = fmaxf(Hacc[2 * at][e], 0.f);
                    Hacc[2 * at + 1][e] = fmaxf(Hacc[2 * at + 1][e], 0.f);
                }
                u32 h0 = pkbf2(Hacc[2 * at][0], Hacc[2 * at][1]);
                u32 h1 = pkbf2(Hacc[2 * at][2], Hacc[2 * at][3]);
                u32 h2 = pkbf2(Hacc[2 * at + 1][0], Hacc[2 * at + 1][1]);
                u32 h3 = pkbf2(Hacc[2 * at + 1][2], Hacc[2 * at + 1][3]);
                int kbase = jc * 8 + at * 2;
#pragma unroll
                for (int nt2 = 0; nt2 < 16; ++nt2) {
                    int row = nt2 * 8 + l7;
                    int ch = kbase + lh;
                    u32 addr = w2base + row * 512 + ((ch ^ l7) << 4);
                    u32 b0, b1; ldsm2(b0, b1, addr);
                    mma16816(Zacc[nt2], h0, h1, h2, h3, b0, b1);
                }
            }
        }
    }

    // ---------- distances from fp32 Zacc ----------
    {
        float ds0 = 0.f, ds1 = 0.f;
#pragma unroll
        for (int nt = 0; nt < 16; ++nt) {
            int col = nt * 8 + gc2;
            float u0 = su[col], u1 = su[col + 1];
            float e;
            e = Zacc[nt][0] + u0; ds0 = fmaf(e, e, ds0);
            e = Zacc[nt][1] + u1; ds0 = fmaf(e, e, ds0);
            e = Zacc[nt][2] + u0; ds1 = fmaf(e, e, ds1);
            e = Zacc[nt][3] + u1; ds1 = fmaf(e, e, ds1);
        }
        ds0 += __shfl_xor_sync(~0u, ds0, 1); ds0 += __shfl_xor_sync(~0u, ds0, 2);
        ds1 += __shfl_xor_sync(~0u, ds1, 1); ds1 += __shfl_xor_sync(~0u, ds1, 2);
        if ((lane & 3) == 0) {
            s_dist[m0 + gr] = ds0;
            s_dist[m0 + gr + 8] = ds1;
        }
    }
    __syncthreads();
    if (t < 256) {
        float m = s_dist[t];
#pragma unroll
        for (int o = 16; o; o >>= 1) m = fminf(m, __shfl_xor_sync(~0u, m, o));
        if ((t & 31) == 0) s_red[t >> 5] = m;
    }
    __syncthreads();
    if (t == 0) {
        float m = s_red[0];
#pragma unroll
        for (int w = 1; w < 8; ++w) m = fminf(m, s_red[w]);
        *(float*)(sm + SM_BC) = m;
    }
    __syncthreads();
    if (t < 256) {
        float dmin = *(float*)(sm + SM_BC);
        if (s_dist[t] <= dmin + MARGIN) {
            int pos = atomicAdd((int*)(sm + SM_CCNT), 1);
            if (pos < 8) ((int*)(sm + SM_CAND))[pos] = t;
        }
    }
    __syncthreads();

    // ---------- exact fp32 rescue ----------
    int ncand = *(int*)(sm + SM_CCNT);
    if (ncand > 8) ncand = 8;
    float* zc = (float*)(sm + SM_ZC);
    float* zb = (float*)(sm + SM_ZB);
    float* sh = (float*)(sm + SM_SH);
    u64 best = ~0ull;
    for (int c = 0; c < ncand; ++c) {
        int k = ((int*)(sm + SM_CAND))[c];
        if (t < 128) zc[t] = g_G[k * 128 + t] + g_V[b * 128 + t];
        __syncthreads();
        for (int L = 0; L < 2; ++L) {
            if (t < 256) {
                const float* wr = (L ? W1_1 : W1_0) + t * 128;
                float a = 0.f;
#pragma unroll 4
                for (int d = 0; d < 128; ++d) a = fmaf(zc[d], wr[d], a);
                sh[t] = fmaxf(a, 0.f);
            }
            __syncthreads();
            float upd = 0.f;
            if (t < 128) {
                const float* w2 = g_W2t + L * 32768 + t;
#pragma unroll 4
                for (int j = 0; j < 256; ++j) upd = fmaf(sh[j], w2[j * 128], upd);
            }
            __syncthreads();
            if (t < 128) zc[t] += upd;
            __syncthreads();
        }
        float p = 0.f;
        if (t < 128) { float e = zc[t] + su[t]; p = e * e; }
#pragma unroll
        for (int o = 16; o; o >>= 1) p += __shfl_xor_sync(~0u, p, o);
        if ((t & 31) == 0 && t < 128) s_red[t >> 5] = p;
        __syncthreads();
        if (t == 0)
            *(float*)(sm + SM_BC) = s_red[0] + s_red[1] + s_red[2] + s_red[3];
        __syncthreads();
        float dc = *(float*)(sm + SM_BC);
        u64 pk = ((u64)__float_as_uint(dc) << 32) | (u32)k;
        if (pk < best) {
            best = pk;
            if (t < 128) zb[t] = zc[t];
        }
        __syncthreads();
    }
    if (t == 0) out[b] = (float)(u32)(best & 0xffffffffu);
    if (t < 128) out[bs + b * 128 + t] = zb[t];
}

// ---------------- launch ----------------
extern "C" void kernel_launch(void* const* d_in, const int* in_sizes, int n_in,
                              void* d_out, int out_size) {
    const float* xhat = (const float*)d_in[0];
    const float* x    = (const float*)d_in[1];
    const float* cb   = (const float*)d_in[2];
    const float* Wc   = (const float*)d_in[3];
    const float* bc   = (const float*)d_in[4];
    const float* W1_0 = (const float*)d_in[5];
    const float* W2_0 = (const float*)d_in[6];
    const float* W1_1 = (const float*)d_in[7];
    const float* W2_1 = (const float*)d_in[8];
    float* out = (float*)d_out;
    const int bs = in_sizes[0] / 128;

    static bool attr = false;
    if (!attr) {
        cudaFuncSetAttribute(k_main, cudaFuncAttributeMaxDynamicSharedMemorySize, SMEMSZ);
        attr = true;
    }

    k_wct<<<256, 128>>>(Wc);
    k_w2t<<<512, 128>>>(W2_0, W2_1);
    k_wb<<<512, 256>>>(W1_0, W1_1, W2_0, W2_1);
    k_G<<<256, 128>>>(cb, bc);
    k_V<<<bs, 128>>>(xhat);
    k_main<<<bs, 512, SMEMSZ>>>(xhat, x, W1_0, W1_1, out, bs);
}